// round 10
// baseline (speedup 1.0000x reference)
#include <cuda_runtime.h>
#include <math.h>

// Hyp-MLR: N=4096, C=256, D=128, CURV=1
// Single fused kernel: dual GEMM (X.P^T, X.A^T) + stats + approx-asinh
// epilogue. R9: 8n x 4c microtile / 128 threads — halves LDS instructions
// and L1 wavefronts per FFMA (4 LDS.128 per 64 FFMA), freeing the L1 pipe
// that was capping the FMA issue rate.

#define N_TOT 4096
#define C_TOT 256
#define D_TOT 128
#define BN 64
#define BC 64
#define KT 64
#define STR 68             // k-major row stride in floats (272B, 16B-aligned)
#define TILE_FLOATS (KT * STR)                  // 4352
#define SMEM_FLOATS (3 * TILE_FLOATS + 4 * 128 + 5 * 64)
#define SMEM_BYTES (SMEM_FLOATS * 4)
#define LN2F 0.69314718055994530942f

__device__ __forceinline__ float fast_rcp(float x) {
    float y; asm("rcp.approx.f32 %0, %1;" : "=f"(y) : "f"(x)); return y;
}
__device__ __forceinline__ float fast_sqrt(float x) {
    float y; asm("sqrt.approx.f32 %0, %1;" : "=f"(y) : "f"(x)); return y;
}
__device__ __forceinline__ float fast_lg2(float x) {
    float y; asm("lg2.approx.f32 %0, %1;" : "=f"(y) : "f"(x)); return y;
}
__device__ __forceinline__ float dot4(float4 a, float4 b) {
    return a.x * b.x + a.y * b.y + a.z * b.z + a.w * b.w;
}

__global__ __launch_bounds__(128, 3) void hyp_mlr_kernel(
    const float* __restrict__ X,   // (N, D)
    const float* __restrict__ A,   // (C, D)
    const float* __restrict__ P,   // (C, D)
    float* __restrict__ out)       // (N, C)
{
    extern __shared__ float smem[];
    float* Xs = smem;                       // [KT][STR] k-major
    float* Ps = smem + TILE_FLOATS;
    float* As = smem + 2 * TILE_FLOATS;
    float* sc_x2 = smem + 3 * TILE_FLOATS;  // [2][64] slab partials
    float* sc_p2 = sc_x2 + 128;
    float* sc_a2 = sc_p2 + 128;
    float* sc_pa = sc_a2 + 128;
    float* sx2  = sc_pa + 128;              // [64] finals
    float* sp2  = sx2 + 64;
    float* spa  = sp2 + 64;
    float* sina = spa + 64;
    float* sw2  = sina + 64;

    const int tid = threadIdx.x;            // 0..127
    const int tx  = tid & 15;   // c dim (16 threads x 4 cols)
    const int ty  = tid >> 4;   // n dim (8 threads x 8 rows)
    const int n0  = blockIdx.y * BN;
    const int c0  = blockIdx.x * BC;

    // Fill mapping: warp spans 32 distinct rows at one k -> conflict-free STS.
    const int frow = tid & 63;          // 0..63
    const int fks  = (tid >> 6) * 32;   // k half-slab start: 0 or 32

    float axp[8][4] = {};   // x.p partials
    float axa[8][4] = {};   // x.a partials
    float x2p = 0.f, p2p = 0.f, a2p = 0.f, pap = 0.f;   // stats partials

    #pragma unroll
    for (int ph = 0; ph < 2; ph++) {
        if (ph) __syncthreads();          // protect smem reuse across phases
        const int kb = ph * KT;
        // Per array: 8 LDG.128 (row-strided; L2-resident) + 32 scalar STS.
        const float* xg = &X[(size_t)(n0 + frow) * D_TOT + kb + fks];
        const float* pg = &P[(size_t)(c0 + frow) * D_TOT + kb + fks];
        const float* ag = &A[(size_t)(c0 + frow) * D_TOT + kb + fks];
        #pragma unroll
        for (int q = 0; q < 8; q++) {
            float4 xv = *(const float4*)&xg[q * 4];
            float4 pv = *(const float4*)&pg[q * 4];
            float4 av = *(const float4*)&ag[q * 4];
            // stats on in-flight data (hidden under LDG latency)
            x2p += dot4(xv, xv);
            p2p += dot4(pv, pv);
            a2p += dot4(av, av);
            pap += dot4(pv, av);
            int k = fks + q * 4;
            Xs[(k + 0) * STR + frow] = xv.x;
            Xs[(k + 1) * STR + frow] = xv.y;
            Xs[(k + 2) * STR + frow] = xv.z;
            Xs[(k + 3) * STR + frow] = xv.w;
            Ps[(k + 0) * STR + frow] = pv.x;
            Ps[(k + 1) * STR + frow] = pv.y;
            Ps[(k + 2) * STR + frow] = pv.z;
            Ps[(k + 3) * STR + frow] = pv.w;
            As[(k + 0) * STR + frow] = av.x;
            As[(k + 1) * STR + frow] = av.y;
            As[(k + 2) * STR + frow] = av.z;
            As[(k + 3) * STR + frow] = av.w;
        }
        __syncthreads();

        // FMA block: per k, 4 LDS.128 feed 64 FFMA (8x4 dual microtile).
        #pragma unroll 2
        for (int k = 0; k < KT; k++) {
            float4 xv0 = *(const float4*)&Xs[k * STR + ty * 8];
            float4 xv1 = *(const float4*)&Xs[k * STR + ty * 8 + 4];
            float4 pv  = *(const float4*)&Ps[k * STR + tx * 4];
            float4 av  = *(const float4*)&As[k * STR + tx * 4];
            float xr[8] = {xv0.x, xv0.y, xv0.z, xv0.w,
                           xv1.x, xv1.y, xv1.z, xv1.w};
            float pr[4] = {pv.x, pv.y, pv.z, pv.w};
            float ar[4] = {av.x, av.y, av.z, av.w};
            #pragma unroll
            for (int i = 0; i < 8; i++)
                #pragma unroll
                for (int j = 0; j < 4; j++) {
                    axp[i][j] = fmaf(xr[i], pr[j], axp[i][j]);
                    axa[i][j] = fmaf(xr[i], ar[j], axa[i][j]);
                }
        }
    }

    // ---- Stats reduction: 2 k-slab partials per row -> finals in smem.
    {
        const int slab = tid >> 6;
        sc_x2[slab * 64 + frow] = x2p;
        sc_p2[slab * 64 + frow] = p2p;
        sc_a2[slab * 64 + frow] = a2p;
        sc_pa[slab * 64 + frow] = pap;
    }
    __syncthreads();
    {
        const int r = tid & 63;
        if (tid < 64) {
            sx2[r] = sc_x2[r] + sc_x2[64 + r];
            sp2[r] = sc_p2[r] + sc_p2[64 + r];
        } else {
            float a2 = sc_a2[r] + sc_a2[64 + r];
            float na = sqrtf(a2);
            sina[r] = fast_rcp(fmaxf(na, 1e-12f));
            sw2[r]  = 2.0f * na * LN2F;
            spa[r]  = sc_pa[r] + sc_pa[64 + r];
        }
    }
    __syncthreads();

    // ---- Epilogue: fused approx hyperbolic math, stats from smem.
    float x2v[8], x2p1[8];
    #pragma unroll
    for (int i = 0; i < 8; i++) {
        x2v[i]  = sx2[ty * 8 + i];
        x2p1[i] = 1.0f + x2v[i];
    }
    float p2v[4], bet[4], bet2[4], pav[4], inav[4], wv[4];
    #pragma unroll
    for (int j = 0; j < 4; j++) {
        p2v[j]  = sp2[tx * 4 + j];
        bet[j]  = 1.0f - p2v[j];
        bet2[j] = bet[j] * bet[j];
        pav[j]  = spa[tx * 4 + j];
        inav[j] = sina[tx * 4 + j];
        wv[j]   = sw2[tx * 4 + j];
    }

    #pragma unroll
    for (int i = 0; i < 8; i++) {
        const int n = n0 + ty * 8 + i;
        float res[4];
        #pragma unroll
        for (int j = 0; j < 4; j++) {
            float xp  = axp[i][j];                   // x.p
            float xa  = axa[i][j];                   // x.a
            float txy = -2.0f * xp;                  // 2*xy (xy = mp.x = -xp)
            float alpha = x2p1[i] + txy;             // 1 + 2xy + x2
            float den   = fmaf(p2v[j], x2v[i], 1.0f + txy);
            // s = ||res||^2 * den^2 = a^2 p2 + a*b*2xy + b^2 x2
            float s   = fmaf(alpha, fmaf(alpha, p2v[j], bet[j] * txy),
                             bet2[j] * x2v[i]);
            float num = fmaf(bet[j], xa, -alpha * pav[j]);   // b*xa - a*pa
            float d2ms = fmaf(den, den, -s);                 // den^2 - s
            // dot*lam = 2*den*num / (na * (den^2 - s))
            float arg = 2.0f * den * num * inav[j] * fast_rcp(d2ms);
            float q   = arg + fast_sqrt(fmaf(arg, arg, 1.0f));
            res[j] = wv[j] * fast_lg2(q);            // 2*na*ln2 * log2(q)
        }
        float4 o = {res[0], res[1], res[2], res[3]};
        *(float4*)&out[(size_t)n * C_TOT + c0 + tx * 4] = o;
    }
}

extern "C" void kernel_launch(void* const* d_in, const int* in_sizes, int n_in,
                              void* d_out, int out_size) {
    const float* X = (const float*)d_in[0];   // output_before (N, D)
    const float* A = (const float*)d_in[1];   // a_mlr (C, D)
    const float* P = (const float*)d_in[2];   // p_mlr (C, D)
    float* out = (float*)d_out;               // (N, C)

    cudaFuncSetAttribute(hyp_mlr_kernel,
                         cudaFuncAttributeMaxDynamicSharedMemorySize,
                         SMEM_BYTES);

    dim3 grid(C_TOT / BC, N_TOT / BN);        // (4, 64) = 256 blocks
    hyp_mlr_kernel<<<grid, 128, SMEM_BYTES>>>(X, A, P, out);
}

// round 12
// speedup vs baseline: 1.3161x; 1.3161x over previous
#include <cuda_runtime.h>
#include <math.h>
#include <stdint.h>

// Hyp-MLR: N=4096, C=256, D=128, CURV=1  — tf32 mma.sync (sm_80 PTX, no
// 'a'-gated features). Per CTA: D[128,128] = X[128rows,128k] · W^T where
// W = [P_blk(64); A_blk(64)]. Precision via 3-pass split:
//   D = Xhi·Whi + Xhi·Wlo + Xlo·Whi   (error ~2^-22, fp32-grade)
// W hi/lo precomputed in smem; X split on the fly in registers.
// Stats (x2,p2,a2,pa) from exact fp32 smem tiles; fused approx-asinh epilogue.

#define N_TOT 4096
#define C_TOT 256
#define D_TOT 128
#define BM   128
#define BCLS 64
#define STRW 132              // smem row stride in floats: bank = (4r+c)&31
#define OFF_X  0
#define OFF_WH (128 * STRW)
#define OFF_WL (2 * 128 * STRW)
#define OFF_ST (3 * 128 * STRW)
#define SMEM_FLOATS (3 * 128 * STRW + 384)
#define SMEM_BYTES  (SMEM_FLOATS * 4)     // 204,288 B
#define LN2F 0.69314718055994530942f

__device__ __forceinline__ float fast_rcp(float x) {
    float y; asm("rcp.approx.f32 %0, %1;" : "=f"(y) : "f"(x)); return y;
}
__device__ __forceinline__ float fast_sqrt(float x) {
    float y; asm("sqrt.approx.f32 %0, %1;" : "=f"(y) : "f"(x)); return y;
}
__device__ __forceinline__ float fast_lg2(float x) {
    float y; asm("lg2.approx.f32 %0, %1;" : "=f"(y) : "f"(x)); return y;
}
__device__ __forceinline__ float dot4(float4 a, float4 b) {
    return a.x * b.x + a.y * b.y + a.z * b.z + a.w * b.w;
}
__device__ __forceinline__ uint32_t cvt_tf32(float x) {
    uint32_t r; asm("cvt.rna.tf32.f32 %0, %1;" : "=r"(r) : "f"(x)); return r;
}
// m16n8k8 tf32 mma: A row-major, B col-major, fp32 accumulate.
__device__ __forceinline__ void mma8(float* c, const uint32_t* a, const uint32_t* b) {
    asm volatile(
        "mma.sync.aligned.m16n8k8.row.col.f32.tf32.tf32.f32 "
        "{%0,%1,%2,%3}, {%4,%5,%6,%7}, {%8,%9}, {%0,%1,%2,%3};"
        : "+f"(c[0]), "+f"(c[1]), "+f"(c[2]), "+f"(c[3])
        : "r"(a[0]), "r"(a[1]), "r"(a[2]), "r"(a[3]), "r"(b[0]), "r"(b[1]));
}

__global__ __launch_bounds__(256, 1) void hyp_mlr_mma_kernel(
    const float* __restrict__ X,   // (N, D)
    const float* __restrict__ A,   // (C, D)
    const float* __restrict__ P,   // (C, D)
    float* __restrict__ out)       // (N, C)
{
    extern __shared__ float sm[];
    float* Xs  = sm + OFF_X;    // [128][STRW] fp32 X tile (later reused as D)
    float* Wh  = sm + OFF_WH;   // [128][STRW] tf32-hi of W = [P;A]
    float* Wl  = sm + OFF_WL;   // [128][STRW] tf32-lo of W
    float* sx2  = sm + OFF_ST;  // [128]
    float* sp2  = sx2 + 128;    // [64]
    float* spa  = sp2 + 64;
    float* sina = spa + 64;
    float* sw2  = sina + 64;

    const int tid = threadIdx.x;
    const int wid = tid >> 5;
    const int lid = tid & 31;
    const int g   = lid >> 2;    // group id (0..7)
    const int tig = lid & 3;     // thread in group
    const int c0  = blockIdx.x * BCLS;
    const int n0  = blockIdx.y * BM;

    // ---- Fill X (fp32, exact) : warp loads one row of 32 float4 per iter.
    #pragma unroll
    for (int i = 0; i < 16; i++) {
        int id  = i * 256 + tid;
        int row = id >> 5;
        int cc  = id & 31;
        float4 v = *(const float4*)&X[(size_t)(n0 + row) * D_TOT + cc * 4];
        *(float4*)&Xs[row * STRW + cc * 4] = v;
    }
    // ---- Fill W split: rows 0-63 = P, 64-127 = A; store tf32 hi + lo.
    #pragma unroll
    for (int i = 0; i < 16; i++) {
        int id  = i * 256 + tid;
        int row = id >> 5;
        int cc  = id & 31;
        const float* src = (row < 64)
            ? &P[(size_t)(c0 + row) * D_TOT]
            : &A[(size_t)(c0 + row - 64) * D_TOT];
        float4 v = *(const float4*)&src[cc * 4];
        float4 h, l;
        h.x = __uint_as_float(cvt_tf32(v.x)); l.x = __uint_as_float(cvt_tf32(v.x - h.x));
        h.y = __uint_as_float(cvt_tf32(v.y)); l.y = __uint_as_float(cvt_tf32(v.y - h.y));
        h.z = __uint_as_float(cvt_tf32(v.z)); l.z = __uint_as_float(cvt_tf32(v.z - h.z));
        h.w = __uint_as_float(cvt_tf32(v.w)); l.w = __uint_as_float(cvt_tf32(v.w - h.w));
        *(float4*)&Wh[row * STRW + cc * 4] = h;
        *(float4*)&Wl[row * STRW + cc * 4] = l;
    }
    __syncthreads();

    // ---- Stats (exact fp32): rows from Xs; classes from Wh+Wl (~1e-7 err).
    if (tid < 128) {
        float s = 0.f;
        #pragma unroll
        for (int cc = 0; cc < 32; cc++) {
            float4 v = *(const float4*)&Xs[tid * STRW + cc * 4];
            s += dot4(v, v);
        }
        sx2[tid] = s;
    } else if (tid < 192) {
        int r = tid - 128;
        float p2 = 0.f, a2 = 0.f, pa = 0.f;
        #pragma unroll
        for (int cc = 0; cc < 32; cc++) {
            float4 ph = *(const float4*)&Wh[r * STRW + cc * 4];
            float4 pl = *(const float4*)&Wl[r * STRW + cc * 4];
            float4 ah = *(const float4*)&Wh[(r + 64) * STRW + cc * 4];
            float4 al = *(const float4*)&Wl[(r + 64) * STRW + cc * 4];
            float4 p = {ph.x + pl.x, ph.y + pl.y, ph.z + pl.z, ph.w + pl.w};
            float4 a = {ah.x + al.x, ah.y + al.y, ah.z + al.z, ah.w + al.w};
            p2 += dot4(p, p);
            a2 += dot4(a, a);
            pa += dot4(p, a);
        }
        sp2[r] = p2;
        spa[r] = pa;
        float na = sqrtf(a2);
        sina[r] = fast_rcp(fmaxf(na, 1e-12f));
        sw2[r]  = 2.0f * na * LN2F;
    }
    // (no sync needed here: stats ordered vs readers by the post-mainloop syncs)

    // ---- Mainloop: warp (wid&3) -> rows, (wid>>2) -> col half (xp | xa).
    const int mrow  = (wid & 3) * 32;
    const int wbase = (wid >> 2) * 64;

    float acc[2][8][4];
    #pragma unroll
    for (int mt = 0; mt < 2; mt++)
        #pragma unroll
        for (int nt = 0; nt < 8; nt++)
            #pragma unroll
            for (int e = 0; e < 4; e++) acc[mt][nt][e] = 0.f;

    #pragma unroll 4
    for (int ks = 0; ks < 16; ks++) {
        const int k0 = ks * 8 + tig;
        // A fragments: load fp32 from Xs, split hi/lo in registers.
        uint32_t ah[2][4], al[2][4];
        #pragma unroll
        for (int mt = 0; mt < 2; mt++) {
            const int rb = (mrow + mt * 16 + g) * STRW;
            float x0 = Xs[rb + k0];
            float x1 = Xs[rb + 8 * STRW + k0];
            float x2 = Xs[rb + k0 + 4];
            float x3 = Xs[rb + 8 * STRW + k0 + 4];
            ah[mt][0] = cvt_tf32(x0); al[mt][0] = cvt_tf32(x0 - __uint_as_float(ah[mt][0]));
            ah[mt][1] = cvt_tf32(x1); al[mt][1] = cvt_tf32(x1 - __uint_as_float(ah[mt][1]));
            ah[mt][2] = cvt_tf32(x2); al[mt][2] = cvt_tf32(x2 - __uint_as_float(ah[mt][2]));
            ah[mt][3] = cvt_tf32(x3); al[mt][3] = cvt_tf32(x3 - __uint_as_float(ah[mt][3]));
        }
        // B fragments: precomputed hi/lo (bank-conflict-free: (4r+c)&31 distinct).
        uint32_t bh[8][2], bl[8][2];
        #pragma unroll
        for (int nt = 0; nt < 8; nt++) {
            const int wr = (wbase + nt * 8 + g) * STRW;
            bh[nt][0] = __float_as_uint(Wh[wr + k0]);
            bh[nt][1] = __float_as_uint(Wh[wr + k0 + 4]);
            bl[nt][0] = __float_as_uint(Wl[wr + k0]);
            bl[nt][1] = __float_as_uint(Wl[wr + k0 + 4]);
        }
        // 3 passes: hi*hi, hi*lo, lo*hi.
        #pragma unroll
        for (int mt = 0; mt < 2; mt++)
            #pragma unroll
            for (int nt = 0; nt < 8; nt++)
                mma8(acc[mt][nt], ah[mt], bh[nt]);
        #pragma unroll
        for (int mt = 0; mt < 2; mt++)
            #pragma unroll
            for (int nt = 0; nt < 8; nt++)
                mma8(acc[mt][nt], ah[mt], bl[nt]);
        #pragma unroll
        for (int mt = 0; mt < 2; mt++)
            #pragma unroll
            for (int nt = 0; nt < 8; nt++)
                mma8(acc[mt][nt], al[mt], bh[nt]);
    }

    // ---- Stage D into smem (reuse Xs area; everyone done reading it).
    __syncthreads();
    float* Ds = Xs;
    #pragma unroll
    for (int mt = 0; mt < 2; mt++)
        #pragma unroll
        for (int nt = 0; nt < 8; nt++) {
            const int r   = mrow + mt * 16 + g;
            const int col = wbase + nt * 8 + tig * 2;
            float2 lo = {acc[mt][nt][0], acc[mt][nt][1]};
            float2 hi = {acc[mt][nt][2], acc[mt][nt][3]};
            *(float2*)&Ds[r * STRW + col]       = lo;
            *(float2*)&Ds[(r + 8) * STRW + col] = hi;
        }
    __syncthreads();

    // ---- Epilogue: thread -> (row = tid/2, 32 classes), fused approx math.
    {
        const int r    = tid >> 1;
        const int ch   = (tid & 1) * 32;
        const float x2   = sx2[r];
        const float x2p1 = 1.0f + x2;
        const size_t obase = (size_t)(n0 + r) * C_TOT + c0 + ch;

        #pragma unroll
        for (int q = 0; q < 8; q++) {
            float4 xp4 = *(const float4*)&Ds[r * STRW + ch + q * 4];
            float4 xa4 = *(const float4*)&Ds[r * STRW + 64 + ch + q * 4];
            float xpv[4] = {xp4.x, xp4.y, xp4.z, xp4.w};
            float xav[4] = {xa4.x, xa4.y, xa4.z, xa4.w};
            float res[4];
            #pragma unroll
            for (int e = 0; e < 4; e++) {
                const int c = ch + q * 4 + e;
                float p2  = sp2[c];
                float bet = 1.0f - p2;
                float txy = -2.0f * xpv[e];              // 2*xy
                float alpha = x2p1 + txy;                // 1 + 2xy + x2
                float den   = fmaf(p2, x2, 1.0f + txy);
                float s   = fmaf(alpha, fmaf(alpha, p2, bet * txy),
                                 bet * bet * x2);
                float num = fmaf(bet, xav[e], -alpha * spa[c]);
                float d2ms = fmaf(den, den, -s);         // den^2 - s
                float arg = 2.0f * den * num * sina[c] * fast_rcp(d2ms);
                float qq  = arg + fast_sqrt(fmaf(arg, arg, 1.0f));
                res[e] = sw2[c] * fast_lg2(qq);          // 2*na*ln2*log2
            }
            float4 o = {res[0], res[1], res[2], res[3]};
            *(float4*)&out[obase + q * 4] = o;
        }
    }
}

extern "C" void kernel_launch(void* const* d_in, const int* in_sizes, int n_in,
                              void* d_out, int out_size) {
    const float* X = (const float*)d_in[0];   // output_before (N, D)
    const float* A = (const float*)d_in[1];   // a_mlr (C, D)
    const float* P = (const float*)d_in[2];   // p_mlr (C, D)
    float* out = (float*)d_out;               // (N, C)

    cudaFuncSetAttribute(hyp_mlr_mma_kernel,
                         cudaFuncAttributeMaxDynamicSharedMemorySize,
                         SMEM_BYTES);

    dim3 grid(C_TOT / BCLS, N_TOT / BM);      // (4, 32) = 128 CTAs, one wave
    hyp_mlr_mma_kernel<<<grid, 256, SMEM_BYTES>>>(X, A, P, out);
}

// round 13
// speedup vs baseline: 1.3361x; 1.0152x over previous
#include <cuda_runtime.h>
#include <math.h>
#include <stdint.h>

// Hyp-MLR: N=4096, C=256, D=128, CURV=1  — tf32 mma.sync (sm_80 PTX).
// Per CTA: D[128,128] = X[128rows,128k] · W^T where W = [P_blk(64); A_blk(64)].
// Precision via 3-pass split: D = Xhi·Whi + Xhi·Wlo + Xlo·Whi (~2^-22 error).
// R12: 512 threads / 16 warps (4m x 4n warp grid) — doubles per-SMSP warp
// concurrency to hide LDS/cvt/mma latency that capped R11 at issue=32%.

#define N_TOT 4096
#define C_TOT 256
#define D_TOT 128
#define BM   128
#define BCLS 64
#define STRW 132              // smem row stride in floats: bank = (4r+c)&31
#define OFF_X  0
#define OFF_WH (128 * STRW)
#define OFF_WL (2 * 128 * STRW)
#define OFF_ST (3 * 128 * STRW)
#define SMEM_FLOATS (3 * 128 * STRW + 384)
#define SMEM_BYTES  (SMEM_FLOATS * 4)     // 204,288 B
#define LN2F 0.69314718055994530942f

__device__ __forceinline__ float fast_rcp(float x) {
    float y; asm("rcp.approx.f32 %0, %1;" : "=f"(y) : "f"(x)); return y;
}
__device__ __forceinline__ float fast_sqrt(float x) {
    float y; asm("sqrt.approx.f32 %0, %1;" : "=f"(y) : "f"(x)); return y;
}
__device__ __forceinline__ float fast_lg2(float x) {
    float y; asm("lg2.approx.f32 %0, %1;" : "=f"(y) : "f"(x)); return y;
}
__device__ __forceinline__ float dot4(float4 a, float4 b) {
    return a.x * b.x + a.y * b.y + a.z * b.z + a.w * b.w;
}
__device__ __forceinline__ uint32_t cvt_tf32(float x) {
    uint32_t r; asm("cvt.rna.tf32.f32 %0, %1;" : "=r"(r) : "f"(x)); return r;
}
// m16n8k8 tf32 mma: A row-major, B col-major, fp32 accumulate.
__device__ __forceinline__ void mma8(float* c, const uint32_t* a, const uint32_t* b) {
    asm volatile(
        "mma.sync.aligned.m16n8k8.row.col.f32.tf32.tf32.f32 "
        "{%0,%1,%2,%3}, {%4,%5,%6,%7}, {%8,%9}, {%0,%1,%2,%3};"
        : "+f"(c[0]), "+f"(c[1]), "+f"(c[2]), "+f"(c[3])
        : "r"(a[0]), "r"(a[1]), "r"(a[2]), "r"(a[3]), "r"(b[0]), "r"(b[1]));
}

__global__ __launch_bounds__(512, 1) void hyp_mlr_mma_kernel(
    const float* __restrict__ X,   // (N, D)
    const float* __restrict__ A,   // (C, D)
    const float* __restrict__ P,   // (C, D)
    float* __restrict__ out)       // (N, C)
{
    extern __shared__ float sm[];
    float* Xs  = sm + OFF_X;    // [128][STRW] fp32 X tile (later reused as D)
    float* Wh  = sm + OFF_WH;   // [128][STRW] tf32-hi of W = [P;A]
    float* Wl  = sm + OFF_WL;   // [128][STRW] tf32-lo of W
    float* sx2  = sm + OFF_ST;  // [128]
    float* sp2  = sx2 + 128;    // [64]
    float* spa  = sp2 + 64;
    float* sina = spa + 64;
    float* sw2  = sina + 64;

    const int tid = threadIdx.x;
    const int wid = tid >> 5;     // 0..15
    const int lid = tid & 31;
    const int g   = lid >> 2;     // group id (0..7)
    const int tig = lid & 3;      // thread in group
    const int c0  = blockIdx.x * BCLS;
    const int n0  = blockIdx.y * BM;

    // ---- Fill X (fp32, exact).
    #pragma unroll
    for (int i = 0; i < 8; i++) {
        int id  = i * 512 + tid;
        int row = id >> 5;
        int cc  = id & 31;
        float4 v = *(const float4*)&X[(size_t)(n0 + row) * D_TOT + cc * 4];
        *(float4*)&Xs[row * STRW + cc * 4] = v;
    }
    // ---- Fill W split: rows 0-63 = P, 64-127 = A; store tf32 hi + lo.
    #pragma unroll
    for (int i = 0; i < 8; i++) {
        int id  = i * 512 + tid;
        int row = id >> 5;
        int cc  = id & 31;
        const float* src = (row < 64)
            ? &P[(size_t)(c0 + row) * D_TOT]
            : &A[(size_t)(c0 + row - 64) * D_TOT];
        float4 v = *(const float4*)&src[cc * 4];
        float4 h, l;
        h.x = __uint_as_float(cvt_tf32(v.x)); l.x = __uint_as_float(cvt_tf32(v.x - h.x));
        h.y = __uint_as_float(cvt_tf32(v.y)); l.y = __uint_as_float(cvt_tf32(v.y - h.y));
        h.z = __uint_as_float(cvt_tf32(v.z)); l.z = __uint_as_float(cvt_tf32(v.z - h.z));
        h.w = __uint_as_float(cvt_tf32(v.w)); l.w = __uint_as_float(cvt_tf32(v.w - h.w));
        *(float4*)&Wh[row * STRW + cc * 4] = h;
        *(float4*)&Wl[row * STRW + cc * 4] = l;
    }
    __syncthreads();

    // ---- Stats (exact fp32): rows from Xs; classes from Wh+Wl (~1e-7 err).
    if (tid < 128) {
        float s = 0.f;
        #pragma unroll
        for (int cc = 0; cc < 32; cc++) {
            float4 v = *(const float4*)&Xs[tid * STRW + cc * 4];
            s += dot4(v, v);
        }
        sx2[tid] = s;
    } else if (tid < 192) {
        int r = tid - 128;
        float p2 = 0.f, a2 = 0.f, pa = 0.f;
        #pragma unroll
        for (int cc = 0; cc < 32; cc++) {
            float4 ph = *(const float4*)&Wh[r * STRW + cc * 4];
            float4 pl = *(const float4*)&Wl[r * STRW + cc * 4];
            float4 ah = *(const float4*)&Wh[(r + 64) * STRW + cc * 4];
            float4 al = *(const float4*)&Wl[(r + 64) * STRW + cc * 4];
            float4 p = {ph.x + pl.x, ph.y + pl.y, ph.z + pl.z, ph.w + pl.w};
            float4 a = {ah.x + al.x, ah.y + al.y, ah.z + al.z, ah.w + al.w};
            p2 += dot4(p, p);
            a2 += dot4(a, a);
            pa += dot4(p, a);
        }
        sp2[r] = p2;
        spa[r] = pa;
        float na = sqrtf(a2);
        sina[r] = fast_rcp(fmaxf(na, 1e-12f));
        sw2[r]  = 2.0f * na * LN2F;
    }
    // stats ordered vs epilogue readers by the post-mainloop __syncthreads

    // ---- Mainloop: warp grid 4m x 4n. wid&3 -> 32-row band, wid>>2 -> 32 cols.
    const int mrow  = (wid & 3) * 32;
    const int wbase = (wid >> 2) * 32;

    float acc[2][4][4];
    #pragma unroll
    for (int mt = 0; mt < 2; mt++)
        #pragma unroll
        for (int nt = 0; nt < 4; nt++)
            #pragma unroll
            for (int e = 0; e < 4; e++) acc[mt][nt][e] = 0.f;

    #pragma unroll 4
    for (int ks = 0; ks < 16; ks++) {
        const int k0 = ks * 8 + tig;
        // A fragments: load fp32 from Xs, split hi/lo in registers.
        uint32_t ah[2][4], al[2][4];
        #pragma unroll
        for (int mt = 0; mt < 2; mt++) {
            const int rb = (mrow + mt * 16 + g) * STRW;
            float x0 = Xs[rb + k0];
            float x1 = Xs[rb + 8 * STRW + k0];
            float x2 = Xs[rb + k0 + 4];
            float x3 = Xs[rb + 8 * STRW + k0 + 4];
            ah[mt][0] = cvt_tf32(x0); al[mt][0] = cvt_tf32(x0 - __uint_as_float(ah[mt][0]));
            ah[mt][1] = cvt_tf32(x1); al[mt][1] = cvt_tf32(x1 - __uint_as_float(ah[mt][1]));
            ah[mt][2] = cvt_tf32(x2); al[mt][2] = cvt_tf32(x2 - __uint_as_float(ah[mt][2]));
            ah[mt][3] = cvt_tf32(x3); al[mt][3] = cvt_tf32(x3 - __uint_as_float(ah[mt][3]));
        }
        // B fragments: precomputed hi/lo (bank-conflict-free: (4r+k)&31 distinct).
        uint32_t bh[4][2], bl[4][2];
        #pragma unroll
        for (int nt = 0; nt < 4; nt++) {
            const int wr = (wbase + nt * 8 + g) * STRW;
            bh[nt][0] = __float_as_uint(Wh[wr + k0]);
            bh[nt][1] = __float_as_uint(Wh[wr + k0 + 4]);
            bl[nt][0] = __float_as_uint(Wl[wr + k0]);
            bl[nt][1] = __float_as_uint(Wl[wr + k0 + 4]);
        }
        // 3 passes: hi*hi, hi*lo, lo*hi.
        #pragma unroll
        for (int mt = 0; mt < 2; mt++)
            #pragma unroll
            for (int nt = 0; nt < 4; nt++)
                mma8(acc[mt][nt], ah[mt], bh[nt]);
        #pragma unroll
        for (int mt = 0; mt < 2; mt++)
            #pragma unroll
            for (int nt = 0; nt < 4; nt++)
                mma8(acc[mt][nt], ah[mt], bl[nt]);
        #pragma unroll
        for (int mt = 0; mt < 2; mt++)
            #pragma unroll
            for (int nt = 0; nt < 4; nt++)
                mma8(acc[mt][nt], al[mt], bh[nt]);
    }

    // ---- Stage D into smem (reuse Xs area; everyone done reading it).
    __syncthreads();
    float* Ds = Xs;
    #pragma unroll
    for (int mt = 0; mt < 2; mt++)
        #pragma unroll
        for (int nt = 0; nt < 4; nt++) {
            const int r   = mrow + mt * 16 + g;
            const int col = wbase + nt * 8 + tig * 2;
            float2 lo = {acc[mt][nt][0], acc[mt][nt][1]};
            float2 hi = {acc[mt][nt][2], acc[mt][nt][3]};
            *(float2*)&Ds[r * STRW + col]       = lo;
            *(float2*)&Ds[(r + 8) * STRW + col] = hi;
        }
    __syncthreads();

    // ---- Epilogue: thread -> (row = tid>>2, 16-class quarter), fused math.
    {
        const int r  = tid >> 2;
        const int ch = (tid & 3) * 16;
        const float x2   = sx2[r];
        const float x2p1 = 1.0f + x2;
        const size_t obase = (size_t)(n0 + r) * C_TOT + c0 + ch;

        #pragma unroll
        for (int q = 0; q < 4; q++) {
            float4 xp4 = *(const float4*)&Ds[r * STRW + ch + q * 4];
            float4 xa4 = *(const float4*)&Ds[r * STRW + 64 + ch + q * 4];
            float xpv[4] = {xp4.x, xp4.y, xp4.z, xp4.w};
            float xav[4] = {xa4.x, xa4.y, xa4.z, xa4.w};
            float res[4];
            #pragma unroll
            for (int e = 0; e < 4; e++) {
                const int c = ch + q * 4 + e;
                float p2  = sp2[c];
                float bet = 1.0f - p2;
                float txy = -2.0f * xpv[e];              // 2*xy
                float alpha = x2p1 + txy;                // 1 + 2xy + x2
                float den   = fmaf(p2, x2, 1.0f + txy);
                float s   = fmaf(alpha, fmaf(alpha, p2, bet * txy),
                                 bet * bet * x2);
                float num = fmaf(bet, xav[e], -alpha * spa[c]);
                float d2ms = fmaf(den, den, -s);         // den^2 - s
                float arg = 2.0f * den * num * sina[c] * fast_rcp(d2ms);
                float qq  = arg + fast_sqrt(fmaf(arg, arg, 1.0f));
                res[e] = sw2[c] * fast_lg2(qq);          // 2*na*ln2*log2
            }
            float4 o = {res[0], res[1], res[2], res[3]};
            *(float4*)&out[obase + q * 4] = o;
        }
    }
}

extern "C" void kernel_launch(void* const* d_in, const int* in_sizes, int n_in,
                              void* d_out, int out_size) {
    const float* X = (const float*)d_in[0];   // output_before (N, D)
    const float* A = (const float*)d_in[1];   // a_mlr (C, D)
    const float* P = (const float*)d_in[2];   // p_mlr (C, D)
    float* out = (float*)d_out;               // (N, C)

    cudaFuncSetAttribute(hyp_mlr_mma_kernel,
                         cudaFuncAttributeMaxDynamicSharedMemorySize,
                         SMEM_BYTES);

    dim3 grid(C_TOT / BCLS, N_TOT / BM);      // (4, 32) = 128 CTAs, one wave
    hyp_mlr_mma_kernel<<<grid, 512, SMEM_BYTES>>>(X, A, P, out);
}

// round 15
// speedup vs baseline: 1.3384x; 1.0017x over previous
#include <cuda_runtime.h>
#include <math.h>
#include <stdint.h>

// Hyp-MLR: N=4096, C=256, D=128, CURV=1  — tf32 mma.sync (sm_80 PTX).
// Per CTA: D[128,128] = X[128rows,128k] · W^T, W = [P_blk(64); A_blk(64)].
// 3-pass split: D = Xh·Wh + Xh·Wl + Xl·Wh.
// R14: hi tiles fp32 (stride 132 >= 128 — R13's fatal bug fixed), lo tiles
// stored as BF16 (|lo| ~ 2^-11|x|; bf16 keeps combined precision ~2^-20).
// Mainloop is pure LDS -> (SHL for lo) -> mma; no cvt chains.

#define N_TOT 4096
#define C_TOT 256
#define D_TOT 128
#define BM   128
#define BCLS 64
#define STRW 132              // stride in elements; 132 % 32 == 4 -> banks 4g+tig
#define TILEE (128 * STRW)    // 16896 elements per tile
// byte layout
#define OFF_XH 0
#define OFF_WH (TILEE * 4)                    // 67584
#define OFF_XL (2 * TILEE * 4)                // 135168 (bf16)
#define OFF_WL (OFF_XL + TILEE * 2)           // 168960 (bf16)
#define OFF_ST (OFF_WL + TILEE * 2)           // 202752
#define SMEM_BYTES (OFF_ST + 384 * 4)         // 204288
#define LN2F 0.69314718055994530942f

__device__ __forceinline__ float fast_rcp(float x) {
    float y; asm("rcp.approx.f32 %0, %1;" : "=f"(y) : "f"(x)); return y;
}
__device__ __forceinline__ float fast_sqrt(float x) {
    float y; asm("sqrt.approx.f32 %0, %1;" : "=f"(y) : "f"(x)); return y;
}
__device__ __forceinline__ float fast_lg2(float x) {
    float y; asm("lg2.approx.f32 %0, %1;" : "=f"(y) : "f"(x)); return y;
}
__device__ __forceinline__ float dot4(float4 a, float4 b) {
    return a.x * b.x + a.y * b.y + a.z * b.z + a.w * b.w;
}
__device__ __forceinline__ uint32_t cvt_tf32(float x) {
    uint32_t r; asm("cvt.rna.tf32.f32 %0, %1;" : "=r"(r) : "f"(x)); return r;
}
// m16n8k8 tf32 mma: A row-major, B col-major, fp32 accumulate.
__device__ __forceinline__ void mma8(float* c, const uint32_t* a, const uint32_t* b) {
    asm volatile(
        "mma.sync.aligned.m16n8k8.row.col.f32.tf32.tf32.f32 "
        "{%0,%1,%2,%3}, {%4,%5,%6,%7}, {%8,%9}, {%0,%1,%2,%3};"
        : "+f"(c[0]), "+f"(c[1]), "+f"(c[2]), "+f"(c[3])
        : "r"(a[0]), "r"(a[1]), "r"(a[2]), "r"(a[3]), "r"(b[0]), "r"(b[1]));
}
__device__ __forceinline__ uint16_t f2bf(float x) {
    uint16_t r; asm("cvt.rn.bf16.f32 %0, %1;" : "=h"(r) : "f"(x)); return r;
}
__device__ __forceinline__ float bf2f(uint16_t u) {
    return __uint_as_float(((uint32_t)u) << 16);
}

__global__ __launch_bounds__(512, 1) void hyp_mlr_mma_kernel(
    const float* __restrict__ X,   // (N, D)
    const float* __restrict__ A,   // (C, D)
    const float* __restrict__ P,   // (C, D)
    float* __restrict__ out)       // (N, C)
{
    extern __shared__ char smem[];
    float*    Xh = (float*)(smem + OFF_XH);      // [128][STRW] tf32-hi of X
    float*    Wh = (float*)(smem + OFF_WH);      // [128][STRW] tf32-hi of W
    uint16_t* Xl = (uint16_t*)(smem + OFF_XL);   // [128][STRW] bf16 lo of X
    uint16_t* Wl = (uint16_t*)(smem + OFF_WL);   // [128][STRW] bf16 lo of W
    float* sx2  = (float*)(smem + OFF_ST);       // [128]
    float* sp2  = sx2 + 128;                     // [64]
    float* spa  = sp2 + 64;
    float* sina = spa + 64;
    float* sw2  = sina + 64;

    const int tid = threadIdx.x;
    const int wid = tid >> 5;     // 0..15
    const int lid = tid & 31;
    const int g   = lid >> 2;     // group id (0..7)
    const int tig = lid & 3;      // thread in group
    const int c0  = blockIdx.x * BCLS;
    const int n0  = blockIdx.y * BM;

    // ---- Fill X: hi (tf32-rna, fp32 tile) + lo (bf16 tile).
    #pragma unroll
    for (int i = 0; i < 8; i++) {
        int id  = i * 512 + tid;
        int row = id >> 5;
        int cc  = id & 31;
        float4 v = *(const float4*)&X[(size_t)(n0 + row) * D_TOT + cc * 4];
        float4 h;
        h.x = __uint_as_float(cvt_tf32(v.x));
        h.y = __uint_as_float(cvt_tf32(v.y));
        h.z = __uint_as_float(cvt_tf32(v.z));
        h.w = __uint_as_float(cvt_tf32(v.w));
        *(float4*)&Xh[row * STRW + cc * 4] = h;
        ushort4 l = {f2bf(v.x - h.x), f2bf(v.y - h.y),
                     f2bf(v.z - h.z), f2bf(v.w - h.w)};
        *(ushort4*)&Xl[row * STRW + cc * 4] = l;
    }
    // ---- Fill W: rows 0-63 = P, 64-127 = A.
    #pragma unroll
    for (int i = 0; i < 8; i++) {
        int id  = i * 512 + tid;
        int row = id >> 5;
        int cc  = id & 31;
        const float* src = (row < 64)
            ? &P[(size_t)(c0 + row) * D_TOT]
            : &A[(size_t)(c0 + row - 64) * D_TOT];
        float4 v = *(const float4*)&src[cc * 4];
        float4 h;
        h.x = __uint_as_float(cvt_tf32(v.x));
        h.y = __uint_as_float(cvt_tf32(v.y));
        h.z = __uint_as_float(cvt_tf32(v.z));
        h.w = __uint_as_float(cvt_tf32(v.w));
        *(float4*)&Wh[row * STRW + cc * 4] = h;
        ushort4 l = {f2bf(v.x - h.x), f2bf(v.y - h.y),
                     f2bf(v.z - h.z), f2bf(v.w - h.w)};
        *(ushort4*)&Wl[row * STRW + cc * 4] = l;
    }
    __syncthreads();

    // ---- Stats from hi+lo tiles (error ~2^-20, immaterial).
    if (tid < 128) {
        float s = 0.f;
        #pragma unroll
        for (int cc = 0; cc < 32; cc++) {
            float4 h = *(const float4*)&Xh[tid * STRW + cc * 4];
            ushort4 l = *(const ushort4*)&Xl[tid * STRW + cc * 4];
            float4 v = {h.x + bf2f(l.x), h.y + bf2f(l.y),
                        h.z + bf2f(l.z), h.w + bf2f(l.w)};
            s += dot4(v, v);
        }
        sx2[tid] = s;
    } else if (tid < 192) {
        int r = tid - 128;
        float p2 = 0.f, a2 = 0.f, pa = 0.f;
        #pragma unroll
        for (int cc = 0; cc < 32; cc++) {
            float4 ph = *(const float4*)&Wh[r * STRW + cc * 4];
            ushort4 pl = *(const ushort4*)&Wl[r * STRW + cc * 4];
            float4 ah = *(const float4*)&Wh[(r + 64) * STRW + cc * 4];
            ushort4 al = *(const ushort4*)&Wl[(r + 64) * STRW + cc * 4];
            float4 p = {ph.x + bf2f(pl.x), ph.y + bf2f(pl.y),
                        ph.z + bf2f(pl.z), ph.w + bf2f(pl.w)};
            float4 a = {ah.x + bf2f(al.x), ah.y + bf2f(al.y),
                        ah.z + bf2f(al.z), ah.w + bf2f(al.w)};
            p2 += dot4(p, p);
            a2 += dot4(a, a);
            pa += dot4(p, a);
        }
        sp2[r] = p2;
        spa[r] = pa;
        float na = sqrtf(a2);
        sina[r] = fast_rcp(fmaxf(na, 1e-12f));
        sw2[r]  = 2.0f * na * LN2F;
    }
    // stats ordered vs epilogue readers by the post-mainloop __syncthreads

    // ---- Mainloop: warp grid 4m x 4n; pure LDS/SHL -> mma.
    const int mrow  = (wid & 3) * 32;
    const int wbase = (wid >> 2) * 32;

    float acc[2][4][4];
    #pragma unroll
    for (int mt = 0; mt < 2; mt++)
        #pragma unroll
        for (int nt = 0; nt < 4; nt++)
            #pragma unroll
            for (int e = 0; e < 4; e++) acc[mt][nt][e] = 0.f;

    #pragma unroll 4
    for (int ks = 0; ks < 16; ks++) {
        const int k0 = ks * 8 + tig;
        // A fragments: hi = direct fp32 LDS; lo = bf16 LDS + SHL (tf32-valid).
        uint32_t ah[2][4], al[2][4];
        #pragma unroll
        for (int mt = 0; mt < 2; mt++) {
            const int rb = (mrow + mt * 16 + g) * STRW;
            ah[mt][0] = __float_as_uint(Xh[rb + k0]);
            ah[mt][1] = __float_as_uint(Xh[rb + 8 * STRW + k0]);
            ah[mt][2] = __float_as_uint(Xh[rb + k0 + 4]);
            ah[mt][3] = __float_as_uint(Xh[rb + 8 * STRW + k0 + 4]);
            al[mt][0] = ((uint32_t)Xl[rb + k0]) << 16;
            al[mt][1] = ((uint32_t)Xl[rb + 8 * STRW + k0]) << 16;
            al[mt][2] = ((uint32_t)Xl[rb + k0 + 4]) << 16;
            al[mt][3] = ((uint32_t)Xl[rb + 8 * STRW + k0 + 4]) << 16;
        }
        // B fragments.
        uint32_t bh[4][2], bl[4][2];
        #pragma unroll
        for (int nt = 0; nt < 4; nt++) {
            const int wr = (wbase + nt * 8 + g) * STRW;
            bh[nt][0] = __float_as_uint(Wh[wr + k0]);
            bh[nt][1] = __float_as_uint(Wh[wr + k0 + 4]);
            bl[nt][0] = ((uint32_t)Wl[wr + k0]) << 16;
            bl[nt][1] = ((uint32_t)Wl[wr + k0 + 4]) << 16;
        }
        // 3 passes: hi*hi, hi*lo, lo*hi.
        #pragma unroll
        for (int mt = 0; mt < 2; mt++)
            #pragma unroll
            for (int nt = 0; nt < 4; nt++)
                mma8(acc[mt][nt], ah[mt], bh[nt]);
        #pragma unroll
        for (int mt = 0; mt < 2; mt++)
            #pragma unroll
            for (int nt = 0; nt < 4; nt++)
                mma8(acc[mt][nt], ah[mt], bl[nt]);
        #pragma unroll
        for (int mt = 0; mt < 2; mt++)
            #pragma unroll
            for (int nt = 0; nt < 4; nt++)
                mma8(acc[mt][nt], al[mt], bh[nt]);
    }

    // ---- Stage D into smem (reuse Xh region: exactly 128*STRW floats).
    __syncthreads();
    float* Ds = Xh;
    #pragma unroll
    for (int mt = 0; mt < 2; mt++)
        #pragma unroll
        for (int nt = 0; nt < 4; nt++) {
            const int r   = mrow + mt * 16 + g;
            const int col = wbase + nt * 8 + tig * 2;
            float2 lo = {acc[mt][nt][0], acc[mt][nt][1]};
            float2 hi = {acc[mt][nt][2], acc[mt][nt][3]};
            *(float2*)&Ds[r * STRW + col]       = lo;
            *(float2*)&Ds[(r + 8) * STRW + col] = hi;
        }
    __syncthreads();

    // ---- Epilogue: thread -> (row = tid>>2, 16-class quarter), fused math.
    {
        const int r  = tid >> 2;
        const int ch = (tid & 3) * 16;
        const float x2   = sx2[r];
        const float x2p1 = 1.0f + x2;
        const size_t obase = (size_t)(n0 + r) * C_TOT + c0 + ch;

        #pragma unroll
        for (int q = 0; q < 4; q++) {
            float4 xp4 = *(const float4*)&Ds[r * STRW + ch + q * 4];
            float4 xa4 = *(const float4*)&Ds[r * STRW + 64 + ch + q * 4];
            float xpv[4] = {xp4.x, xp4.y, xp4.z, xp4.w};
            float xav[4] = {xa4.x, xa4.y, xa4.z, xa4.w};
            float res[4];
            #pragma unroll
            for (int e = 0; e < 4; e++) {
                const int c = ch + q * 4 + e;
                float p2  = sp2[c];
                float bet = 1.0f - p2;
                float txy = -2.0f * xpv[e];              // 2*xy
                float alpha = x2p1 + txy;                // 1 + 2xy + x2
                float den   = fmaf(p2, x2, 1.0f + txy);
                float s   = fmaf(alpha, fmaf(alpha, p2, bet * txy),
                                 bet * bet * x2);
                float num = fmaf(bet, xav[e], -alpha * spa[c]);
                float d2ms = fmaf(den, den, -s);         // den^2 - s
                float arg = 2.0f * den * num * sina[c] * fast_rcp(d2ms);
                float qq  = arg + fast_sqrt(fmaf(arg, arg, 1.0f));
                res[e] = sw2[c] * fast_lg2(qq);          // 2*na*ln2*log2
            }
            float4 o = {res[0], res[1], res[2], res[3]};
            *(float4*)&out[obase + q * 4] = o;
        }
    }
}

extern "C" void kernel_launch(void* const* d_in, const int* in_sizes, int n_in,
                              void* d_out, int out_size) {
    const float* X = (const float*)d_in[0];   // output_before (N, D)
    const float* A = (const float*)d_in[1];   // a_mlr (C, D)
    const float* P = (const float*)d_in[2];   // p_mlr (C, D)
    float* out = (float*)d_out;               // (N, C)

    cudaFuncSetAttribute(hyp_mlr_mma_kernel,
                         cudaFuncAttributeMaxDynamicSharedMemorySize,
                         SMEM_BYTES);

    dim3 grid(C_TOT / BCLS, N_TOT / BM);      // (4, 32) = 128 CTAs, one wave
    hyp_mlr_mma_kernel<<<grid, 512, SMEM_BYTES>>>(X, A, P, out);
}